// round 7
// baseline (speedup 1.0000x reference)
#include <cuda_runtime.h>
#include <math.h>
#include <stdint.h>

// Problem constants
#define BATCH   4
#define SEQLEN  2048
#define DMODEL  1024
#define NHEAD   16
#define HEADDIM 64
#define MROWS   (BATCH * SEQLEN)   // 8192

// Scratch (device globals: no allocation allowed in kernel_launch)
__device__ float g_q[(size_t)BATCH * NHEAD * SEQLEN * HEADDIM];    // [B,H,L,hd]
__device__ float g_k[(size_t)BATCH * NHEAD * SEQLEN * HEADDIM];
__device__ float g_v[(size_t)BATCH * NHEAD * SEQLEN * HEADDIM];
__device__ float g_attn[(size_t)MROWS * DMODEL];                   // [B,L,H*hd]

// ---------------------------------------------------------------------------
// TF32 mma helpers
// ---------------------------------------------------------------------------
__device__ __forceinline__ uint32_t f2tf32(float f) {
    uint32_t u;
    asm("cvt.rna.tf32.f32 %0, %1;" : "=r"(u) : "f"(f));
    return u;
}

__device__ __forceinline__ void mma_tf32(float* d, const uint32_t* a,
                                         uint32_t b0, uint32_t b1) {
    asm volatile(
        "mma.sync.aligned.m16n8k8.row.col.f32.tf32.tf32.f32 "
        "{%0,%1,%2,%3}, {%4,%5,%6,%7}, {%8,%9}, {%0,%1,%2,%3};\n"
        : "+f"(d[0]), "+f"(d[1]), "+f"(d[2]), "+f"(d[3])
        : "r"(a[0]), "r"(a[1]), "r"(a[2]), "r"(a[3]), "r"(b0), "r"(b1));
}

// ---------------------------------------------------------------------------
// TF32 GEMM: C[m,n] = sum_k A[m,k] * W[n,k] + bias[n]
// Block 128x128, BK=16, 128 threads (4 warps, 2x2), warp tile 64x64.
// sel 0: -> g_q scatter [B,H,L,hd], RoPE + 1/8 scale fused in epilogue
// sel 1: -> g_k scatter, RoPE fused
// sel 2: -> g_v scatter, plain
// sel 3: A = g_attn -> C_out row-major [M, DMODEL], plain
// ---------------------------------------------------------------------------
__global__ __launch_bounds__(128) void gemm_tf32(const float* __restrict__ A_in,
                                                 const float* __restrict__ W,
                                                 const float* __restrict__ bias,
                                                 float* __restrict__ C_out,
                                                 int sel)
{
    __shared__ float As[128][20];   // stride 20: frag reads conflict-free
    __shared__ float Ws[128][20];

    const int K = DMODEL;
    const float* A = (sel == 3) ? g_attn : A_in;
    float* C;
    if (sel == 0)      C = g_q;
    else if (sel == 1) C = g_k;
    else if (sel == 2) C = g_v;
    else               C = C_out;

    const int tid  = threadIdx.x;
    const int w    = tid >> 5;
    const int lane = tid & 31;
    const int g    = lane >> 2;
    const int q    = lane & 3;
    const int wm   = (w & 1) * 64;     // warp m-offset
    const int wn   = (w >> 1) * 64;    // warp n-offset (64-wide => head-aligned)

    const int m0 = blockIdx.y * 128;
    const int n0 = blockIdx.x * 128;

    const float* Aptr = A + (size_t)m0 * K;
    const float* Wptr = W + (size_t)n0 * K;

    // Global-load mapping: idx = tid + i*128 in [0,512); row=idx>>2, c4=(idx&3)*4
    int ld_row[4], ld_c4[4];
#pragma unroll
    for (int i = 0; i < 4; i++) {
        int idx = tid + i * 128;
        ld_row[i] = idx >> 2;
        ld_c4[i]  = (idx & 3) * 4;
    }

    float acc[4][8][4];
#pragma unroll
    for (int mi = 0; mi < 4; mi++)
#pragma unroll
        for (int nj = 0; nj < 8; nj++)
#pragma unroll
            for (int c = 0; c < 4; c++) acc[mi][nj][c] = 0.0f;

    // Prefetch tile 0
    float4 pa[4], pw[4];
#pragma unroll
    for (int i = 0; i < 4; i++) {
        pa[i] = *reinterpret_cast<const float4*>(Aptr + (size_t)ld_row[i] * K + ld_c4[i]);
        pw[i] = *reinterpret_cast<const float4*>(Wptr + (size_t)ld_row[i] * K + ld_c4[i]);
    }

    for (int kt = 0; kt < K; kt += 16) {
        // Store prefetched tile (tf32-converted)
#pragma unroll
        for (int i = 0; i < 4; i++) {
            float4 a = pa[i], t;
            t.x = __uint_as_float(f2tf32(a.x));
            t.y = __uint_as_float(f2tf32(a.y));
            t.z = __uint_as_float(f2tf32(a.z));
            t.w = __uint_as_float(f2tf32(a.w));
            *reinterpret_cast<float4*>(&As[ld_row[i]][ld_c4[i]]) = t;
            float4 b = pw[i];
            t.x = __uint_as_float(f2tf32(b.x));
            t.y = __uint_as_float(f2tf32(b.y));
            t.z = __uint_as_float(f2tf32(b.z));
            t.w = __uint_as_float(f2tf32(b.w));
            *reinterpret_cast<float4*>(&Ws[ld_row[i]][ld_c4[i]]) = t;
        }
        __syncthreads();

        if (kt + 16 < K) {
#pragma unroll
            for (int i = 0; i < 4; i++) {
                pa[i] = *reinterpret_cast<const float4*>(
                    Aptr + (size_t)ld_row[i] * K + kt + 16 + ld_c4[i]);
                pw[i] = *reinterpret_cast<const float4*>(
                    Wptr + (size_t)ld_row[i] * K + kt + 16 + ld_c4[i]);
            }
        }

#pragma unroll
        for (int kc = 0; kc < 2; kc++) {
            const int k0 = kc * 8;
            uint32_t a[4][4];
#pragma unroll
            for (int mi = 0; mi < 4; mi++) {
                int r = wm + mi * 16;
                a[mi][0] = __float_as_uint(As[r + g][k0 + q]);
                a[mi][1] = __float_as_uint(As[r + 8 + g][k0 + q]);
                a[mi][2] = __float_as_uint(As[r + g][k0 + q + 4]);
                a[mi][3] = __float_as_uint(As[r + 8 + g][k0 + q + 4]);
            }
            uint32_t b[8][2];
#pragma unroll
            for (int nj = 0; nj < 8; nj++) {
                int bn = wn + nj * 8;
                b[nj][0] = __float_as_uint(Ws[bn + g][k0 + q]);
                b[nj][1] = __float_as_uint(Ws[bn + g][k0 + q + 4]);
            }
#pragma unroll
            for (int mi = 0; mi < 4; mi++)
#pragma unroll
                for (int nj = 0; nj < 8; nj++)
                    mma_tf32(acc[mi][nj], a[mi], b[nj][0], b[nj][1]);
        }
        __syncthreads();
    }

    // ---- Epilogue ----
    if (sel <= 1) {
        // Q/K: fused RoPE. Warp n-tile is 64-wide and head-aligned, so the
        // rotation pair (d, d+32) is (nj, nj+4) in this thread.
        const float cfrq  = 9.210340371976184f / 32.0f;   // ln(10000)/32
        const float scale = (sel == 0) ? 0.125f : 1.0f;
#pragma unroll
        for (int nj = 0; nj < 4; nj++) {
            int cn = n0 + wn + nj * 8 + 2 * q;   // lo column
            int d0 = cn & 63;                    // = nj*8 + 2q  (< 32)
            int h_ = cn >> 6;
            float if0 = __expf(-(float)d0 * cfrq);
            float if1 = __expf(-(float)(d0 + 1) * cfrq);
            float bl0 = bias[cn],      bl1 = bias[cn + 1];
            float bh0 = bias[cn + 32], bh1 = bias[cn + 33];
#pragma unroll
            for (int mi = 0; mi < 4; mi++) {
#pragma unroll
                for (int rr = 0; rr < 2; rr++) {
                    int m  = m0 + wm + mi * 16 + g + rr * 8;
                    int b_ = m >> 11, l_ = m & 2047;
                    float lo0 = acc[mi][nj][rr * 2 + 0] + bl0;
                    float lo1 = acc[mi][nj][rr * 2 + 1] + bl1;
                    float hi0 = acc[mi][nj + 4][rr * 2 + 0] + bh0;
                    float hi1 = acc[mi][nj + 4][rr * 2 + 1] + bh1;
                    float sn0, cs0, sn1, cs1;
                    sincosf((float)l_ * if0, &sn0, &cs0);
                    sincosf((float)l_ * if1, &sn1, &cs1);
                    float2 vlo = make_float2((lo0 * cs0 - hi0 * sn0) * scale,
                                             (lo1 * cs1 - hi1 * sn1) * scale);
                    float2 vhi = make_float2((hi0 * cs0 + lo0 * sn0) * scale,
                                             (hi1 * cs1 + lo1 * sn1) * scale);
                    size_t base = (((size_t)(b_ * NHEAD + h_)) * SEQLEN + l_) * HEADDIM;
                    *reinterpret_cast<float2*>(C + base + d0)      = vlo;
                    *reinterpret_cast<float2*>(C + base + d0 + 32) = vhi;
                }
            }
        }
    } else {
#pragma unroll
        for (int nj = 0; nj < 8; nj++) {
            int cn = n0 + wn + nj * 8 + 2 * q;
            float b0 = bias[cn];
            float b1 = bias[cn + 1];
#pragma unroll
            for (int mi = 0; mi < 4; mi++) {
#pragma unroll
                for (int rr = 0; rr < 2; rr++) {
                    int m  = m0 + wm + mi * 16 + g + rr * 8;
                    float2 v = make_float2(acc[mi][nj][rr * 2 + 0] + b0,
                                           acc[mi][nj][rr * 2 + 1] + b1);
                    if (sel == 2) {
                        int h_ = cn >> 6;
                        int d_ = cn & 63;
                        int b_ = m >> 11, l_ = m & 2047;
                        *reinterpret_cast<float2*>(
                            C + (((size_t)(b_ * NHEAD + h_)) * SEQLEN + l_) * HEADDIM + d_) = v;
                    } else {
                        *reinterpret_cast<float2*>(C + (size_t)m * DMODEL + cn) = v;
                    }
                }
            }
        }
    }
}

// ---------------------------------------------------------------------------
// Flash attention, tf32 mma, RoPE precomputed. (unchanged from round 6)
// Grid: (L/128, B*H). Block: 256 threads (8 warps), 1 m-frag per warp.
// ---------------------------------------------------------------------------
__global__ __launch_bounds__(256, 2) void attn_mma_kernel()
{
    __shared__ float smem_all[64 * 68 + 64 * 72];   // 35840 B
    float (*Ks)[68] = (float(*)[68])smem_all;
    float (*Vs)[72] = (float(*)[72])(smem_all + 64 * 68);
    float (*Qs)[68] = (float(*)[68])smem_all;

    const int tid  = threadIdx.x;
    const int w    = tid >> 5;
    const int lane = tid & 31;
    const int g    = lane >> 2;
    const int q    = lane & 3;

    const int bh = blockIdx.y;
    const int b_ = bh >> 4;
    const int h_ = bh & 15;
    const int q0 = blockIdx.x * 128;

    const float* Qg = g_q + (size_t)bh * SEQLEN * HEADDIM;
    const float* Kg = g_k + (size_t)bh * SEQLEN * HEADDIM;
    const float* Vg = g_v + (size_t)bh * SEQLEN * HEADDIM;

#pragma unroll
    for (int i = 0; i < 8; i++) {
        int idx = tid + i * 256;
        int r = idx >> 4;
        int cv = (idx & 15) * 4;
        float4 v = *reinterpret_cast<const float4*>(Qg + (size_t)(q0 + r) * HEADDIM + cv);
        Qs[r][cv + 0] = v.x; Qs[r][cv + 1] = v.y;
        Qs[r][cv + 2] = v.z; Qs[r][cv + 3] = v.w;
    }
    __syncthreads();

    uint32_t aq[8][4];
    {
        int row0 = w * 16 + g;
#pragma unroll
        for (int kc = 0; kc < 8; kc++) {
            int c0 = kc * 8 + q;
            aq[kc][0] = f2tf32(Qs[row0][c0]);
            aq[kc][1] = f2tf32(Qs[row0 + 8][c0]);
            aq[kc][2] = f2tf32(Qs[row0][c0 + 4]);
            aq[kc][3] = f2tf32(Qs[row0 + 8][c0 + 4]);
        }
    }

    float o[8][4];
    float mA = -INFINITY, mB = -INFINITY, lA = 0.0f, lB = 0.0f;
#pragma unroll
    for (int n = 0; n < 8; n++)
#pragma unroll
        for (int c = 0; c < 4; c++) o[n][c] = 0.0f;

    for (int kk = 0; kk < 32; kk++) {
        const int kv0 = kk * 64;
        __syncthreads();

#pragma unroll
        for (int i = 0; i < 4; i++) {
            int idx = tid + i * 256;
            int r = idx >> 4;
            int cv = (idx & 15) * 4;
            float4 kv = *reinterpret_cast<const float4*>(Kg + (size_t)(kv0 + r) * HEADDIM + cv);
            Ks[r][cv + 0] = __uint_as_float(f2tf32(kv.x));
            Ks[r][cv + 1] = __uint_as_float(f2tf32(kv.y));
            Ks[r][cv + 2] = __uint_as_float(f2tf32(kv.z));
            Ks[r][cv + 3] = __uint_as_float(f2tf32(kv.w));
            float4 vv = *reinterpret_cast<const float4*>(Vg + (size_t)(kv0 + r) * HEADDIM + cv);
            Vs[r][cv + 0] = __uint_as_float(f2tf32(vv.x));
            Vs[r][cv + 1] = __uint_as_float(f2tf32(vv.y));
            Vs[r][cv + 2] = __uint_as_float(f2tf32(vv.z));
            Vs[r][cv + 3] = __uint_as_float(f2tf32(vv.w));
        }
        __syncthreads();

        float s[8][4];
#pragma unroll
        for (int n = 0; n < 8; n++)
#pragma unroll
            for (int c = 0; c < 4; c++) s[n][c] = 0.0f;

#pragma unroll
        for (int n = 0; n < 8; n++) {
#pragma unroll
            for (int kc = 0; kc < 8; kc++) {
                uint32_t b0 = __float_as_uint(Ks[n * 8 + g][kc * 8 + q]);
                uint32_t b1 = __float_as_uint(Ks[n * 8 + g][kc * 8 + q + 4]);
                mma_tf32(s[n], aq[kc], b0, b1);
            }
        }

        {
            float mxA = -1e30f, mxB = -1e30f;
#pragma unroll
            for (int n = 0; n < 8; n++) {
                mxA = fmaxf(mxA, fmaxf(s[n][0], s[n][1]));
                mxB = fmaxf(mxB, fmaxf(s[n][2], s[n][3]));
            }
            mxA = fmaxf(mxA, __shfl_xor_sync(0xffffffffu, mxA, 1));
            mxA = fmaxf(mxA, __shfl_xor_sync(0xffffffffu, mxA, 2));
            mxB = fmaxf(mxB, __shfl_xor_sync(0xffffffffu, mxB, 1));
            mxB = fmaxf(mxB, __shfl_xor_sync(0xffffffffu, mxB, 2));
            float mnA = fmaxf(mA, mxA);
            float mnB = fmaxf(mB, mxB);
            float cA = __expf(mA - mnA);
            float cB = __expf(mB - mnB);
            float rsA = 0.0f, rsB = 0.0f;
#pragma unroll
            for (int n = 0; n < 8; n++) {
                s[n][0] = __expf(s[n][0] - mnA); rsA += s[n][0];
                s[n][1] = __expf(s[n][1] - mnA); rsA += s[n][1];
                s[n][2] = __expf(s[n][2] - mnB); rsB += s[n][2];
                s[n][3] = __expf(s[n][3] - mnB); rsB += s[n][3];
                o[n][0] *= cA; o[n][1] *= cA;
                o[n][2] *= cB; o[n][3] *= cB;
            }
            rsA += __shfl_xor_sync(0xffffffffu, rsA, 1);
            rsA += __shfl_xor_sync(0xffffffffu, rsA, 2);
            rsB += __shfl_xor_sync(0xffffffffu, rsB, 1);
            rsB += __shfl_xor_sync(0xffffffffu, rsB, 2);
            lA = lA * cA + rsA; mA = mnA;
            lB = lB * cB + rsB; mB = mnB;
        }

        const int src0 = (g << 2) + (q >> 1);
        const int src1 = src0 + 2;
        const bool odd = (q & 1);
#pragma unroll
        for (int kc = 0; kc < 8; kc++) {
            uint32_t ap[4];
            float v00 = __shfl_sync(0xffffffffu, s[kc][0], src0);
            float v01 = __shfl_sync(0xffffffffu, s[kc][1], src0);
            float v02 = __shfl_sync(0xffffffffu, s[kc][2], src0);
            float v03 = __shfl_sync(0xffffffffu, s[kc][3], src0);
            float v10 = __shfl_sync(0xffffffffu, s[kc][0], src1);
            float v11 = __shfl_sync(0xffffffffu, s[kc][1], src1);
            float v12 = __shfl_sync(0xffffffffu, s[kc][2], src1);
            float v13 = __shfl_sync(0xffffffffu, s[kc][3], src1);
            ap[0] = f2tf32(odd ? v01 : v00);
            ap[1] = f2tf32(odd ? v03 : v02);
            ap[2] = f2tf32(odd ? v11 : v10);
            ap[3] = f2tf32(odd ? v13 : v12);
#pragma unroll
            for (int n = 0; n < 8; n++) {
                uint32_t b0 = __float_as_uint(Vs[kc * 8 + q][n * 8 + g]);
                uint32_t b1 = __float_as_uint(Vs[kc * 8 + q + 4][n * 8 + g]);
                mma_tf32(o[n], ap, b0, b1);
            }
        }
    }

    {
        float iA = 1.0f / lA;
        float iB = 1.0f / lB;
        int row0 = q0 + w * 16 + g;
#pragma unroll
        for (int n = 0; n < 8; n++) {
            int col = n * 8 + 2 * q;
            float2 r0v = make_float2(o[n][0] * iA, o[n][1] * iA);
            float2 r1v = make_float2(o[n][2] * iB, o[n][3] * iB);
            *reinterpret_cast<float2*>(
                g_attn + ((size_t)(b_ * SEQLEN + row0) * NHEAD + h_) * HEADDIM + col) = r0v;
            *reinterpret_cast<float2*>(
                g_attn + ((size_t)(b_ * SEQLEN + row0 + 8) * NHEAD + h_) * HEADDIM + col) = r1v;
        }
    }
}

// ---------------------------------------------------------------------------
extern "C" void kernel_launch(void* const* d_in, const int* in_sizes, int n_in,
                              void* d_out, int out_size)
{
    const float* x  = (const float*)d_in[0];
    const float* Wq = (const float*)d_in[1];
    const float* bq = (const float*)d_in[2];
    const float* Wk = (const float*)d_in[3];
    const float* bk = (const float*)d_in[4];
    const float* Wv = (const float*)d_in[5];
    const float* bv = (const float*)d_in[6];
    const float* Wo = (const float*)d_in[7];
    const float* bo = (const float*)d_in[8];
    float* out = (float*)d_out;

    dim3 ggrid(DMODEL / 128, MROWS / 128);   // (8, 64)
    gemm_tf32<<<ggrid, 128>>>(x, Wq, bq, nullptr, 0);
    gemm_tf32<<<ggrid, 128>>>(x, Wk, bk, nullptr, 1);
    gemm_tf32<<<ggrid, 128>>>(x, Wv, bv, nullptr, 2);

    attn_mma_kernel<<<dim3(SEQLEN / 128, BATCH * NHEAD), 256>>>();

    gemm_tf32<<<ggrid, 128>>>(nullptr, Wo, bo, out, 3);
}